// round 1
// baseline (speedup 1.0000x reference)
#include <cuda_runtime.h>
#include <math.h>

// Problem constants (fixed shapes per reference)
#define NFK 4096
#define NRK 8192
#define NTH 256
#define NT 4                   // r rows per thread
#define RBLK (NTH*NT)          // 1024 r per block
#define FCHUNK 128             // f columns per block
#define NCH (NFK/FCHUNK)       // 32
#define NRB (NRK/RBLK)         // 8

#define EPS_CH   1e-5f
#define EPS_ACOS 1e-6f
#define PI_F     3.14159265358979323846f

// ---------------- scratch (static device memory: allocation-free) ----------------
__device__ float    g_fpack[NFK * 16];   // per f: tf.xyz, nf, R0..R8, pad3
__device__ float    g_nr[NRK];           // |tb|^2 per r
__device__ unsigned g_minu[NRK];         // min over f of (nf - 2 dot), ord-encoded
__device__ unsigned g_maxtrR[NRK];       // max over f of trace, ord-encoded
__device__ unsigned g_minv[NFK];         // min over r of (nr - 2 dot), ord-encoded
__device__ unsigned g_maxtrF[NFK];       // max over r of trace, ord-encoded

// Order-preserving float<->uint mapping so atomicMin/atomicMax work on floats.
__device__ __forceinline__ unsigned ford(float f) {
    unsigned u = __float_as_uint(f);
    return (u & 0x80000000u) ? ~u : (u | 0x80000000u);
}
__device__ __forceinline__ float finv(unsigned u) {
    return __uint_as_float((u & 0x80000000u) ? (u & 0x7fffffffu) : ~u);
}

// ---------------- init: pack f-side, norms, reset scratch ----------------
__global__ void init_kernel(const float* __restrict__ t_fake,
                            const float* __restrict__ R_fake,
                            const float* __restrict__ t_buffer) {
    int i = blockIdx.x * blockDim.x + threadIdx.x;
    if (i < NFK) {
        float tx = t_fake[i*3+0], ty = t_fake[i*3+1], tz = t_fake[i*3+2];
        float nf = fmaf(tx, tx, fmaf(ty, ty, tz*tz));
        float* p = &g_fpack[i*16];
        p[0] = tx; p[1] = ty; p[2] = tz; p[3] = nf;
        #pragma unroll
        for (int k = 0; k < 9; k++) p[4+k] = R_fake[i*9+k];
        p[13] = 0.f; p[14] = 0.f; p[15] = 0.f;
        g_minv[i]   = 0xFFFFFFFFu;
        g_maxtrF[i] = 0u;
    }
    if (i < NRK) {
        float tx = t_buffer[i*3+0], ty = t_buffer[i*3+1], tz = t_buffer[i*3+2];
        g_nr[i] = fmaf(tx, tx, fmaf(ty, ty, tz*tz));
        g_minu[i]   = 0xFFFFFFFFu;
        g_maxtrR[i] = 0u;
    }
}

// ---------------- main all-pairs kernel ----------------
__global__ __launch_bounds__(NTH, 2)
void pair_kernel(const float* __restrict__ r_buffer,
                 const float* __restrict__ t_buffer) {
    __shared__ float4 sf[FCHUNK * 4];       // 8 KB: staged f-side tile

    const int fbase = blockIdx.x * FCHUNK;
    const int rbase = blockIdx.y * RBLK;
    const int tid   = threadIdx.x;

    // Stage f tile from packed global into shared (float4 copies).
    {
        const float4* gp = reinterpret_cast<const float4*>(&g_fpack[fbase * 16]);
        #pragma unroll
        for (int i = tid; i < FCHUNK * 4; i += NTH) sf[i] = gp[i];
    }
    __syncthreads();

    // Per-thread r rows in registers.
    const int r0 = rbase + tid * NT;
    float Rr[NT][9], tb[NT][3], nr[NT];
    #pragma unroll
    for (int j = 0; j < NT; j++) {
        const float* rp = &r_buffer[(r0 + j) * 9];
        #pragma unroll
        for (int k = 0; k < 9; k++) Rr[j][k] = rp[k];
        const float* tp = &t_buffer[(r0 + j) * 3];
        tb[j][0] = tp[0]; tb[j][1] = tp[1]; tb[j][2] = tp[2];
        nr[j] = g_nr[r0 + j];
    }

    const float INF = __int_as_float(0x7f800000);
    float minu[NT], maxtr[NT];
    #pragma unroll
    for (int j = 0; j < NT; j++) { minu[j] = INF; maxtr[j] = -INF; }

    #pragma unroll 2
    for (int f = 0; f < FCHUNK; f++) {
        const float4 a = sf[f*4+0];   // tf.xyz, nf
        const float4 b = sf[f*4+1];   // R0..R3
        const float4 c = sf[f*4+2];   // R4..R7
        const float4 d = sf[f*4+3];   // R8, pad

        float fminv = INF;
        float fmaxt = -INF;

        #pragma unroll
        for (int j = 0; j < NT; j++) {
            float dot = fmaf(tb[j][0], a.x, fmaf(tb[j][1], a.y, tb[j][2] * a.z));
            float u = fmaf(dot, -2.0f, a.w);     // nf - 2 dot
            float v = fmaf(dot, -2.0f, nr[j]);   // nr - 2 dot

            float tr = Rr[j][0] * b.x;
            tr = fmaf(Rr[j][1], b.y, tr);
            tr = fmaf(Rr[j][2], b.z, tr);
            tr = fmaf(Rr[j][3], b.w, tr);
            tr = fmaf(Rr[j][4], c.x, tr);
            tr = fmaf(Rr[j][5], c.y, tr);
            tr = fmaf(Rr[j][6], c.z, tr);
            tr = fmaf(Rr[j][7], c.w, tr);
            tr = fmaf(Rr[j][8], d.x, tr);

            minu[j]  = fminf(minu[j], u);
            maxtr[j] = fmaxf(maxtr[j], tr);
            fminv    = fminf(fminv, v);
            fmaxt    = fmaxf(fmaxt, tr);
        }

        // Per-f reduction across the warp's 32 lanes (each lane = distinct r's).
        #pragma unroll
        for (int off = 16; off; off >>= 1) {
            fminv = fminf(fminv, __shfl_xor_sync(0xffffffffu, fminv, off));
            fmaxt = fmaxf(fmaxt, __shfl_xor_sync(0xffffffffu, fmaxt, off));
        }
        if ((tid & 31) == 0) {
            atomicMin(&g_minv[fbase + f],   ford(fminv));   // RED (no return)
            atomicMax(&g_maxtrF[fbase + f], ford(fmaxt));
        }
    }

    // Merge per-r partials (one pair of atomics per r per f-chunk).
    #pragma unroll
    for (int j = 0; j < NT; j++) {
        atomicMin(&g_minu[r0 + j],   ford(minu[j]));
        atomicMax(&g_maxtrR[r0 + j], ford(maxtr[j]));
    }
}

// ---------------- epilogue: sqrt/acos + reduction to scalar ----------------
__global__ void final_kernel(float* __restrict__ out) {
    const int tid = threadIdx.x;
    float sAngR = 0.f, sSqR = 0.f, sAngF = 0.f, sSqF = 0.f;

    for (int i = tid; i < NRK; i += NTH) {
        float mu = finv(g_minu[i]);
        float td = fmaxf(g_nr[i] + mu, 0.0f);
        sSqR += sqrtf(td + EPS_CH);
        float tr = finv(g_maxtrR[i]);
        float cs = 0.5f * (tr - 1.0f);
        cs = fminf(fmaxf(cs, -1.0f + EPS_ACOS), 1.0f - EPS_ACOS);
        sAngR += acosf(cs);
    }
    for (int i = tid; i < NFK; i += NTH) {
        float mv = finv(g_minv[i]);
        float nf = g_fpack[i*16 + 3];
        float td = fmaxf(nf + mv, 0.0f);
        sSqF += sqrtf(td + EPS_CH);
        float tr = finv(g_maxtrF[i]);
        float cs = 0.5f * (tr - 1.0f);
        cs = fminf(fmaxf(cs, -1.0f + EPS_ACOS), 1.0f - EPS_ACOS);
        sAngF += acosf(cs);
    }

    // warp reduce
    #pragma unroll
    for (int off = 16; off; off >>= 1) {
        sAngR += __shfl_xor_sync(0xffffffffu, sAngR, off);
        sSqR  += __shfl_xor_sync(0xffffffffu, sSqR,  off);
        sAngF += __shfl_xor_sync(0xffffffffu, sAngF, off);
        sSqF  += __shfl_xor_sync(0xffffffffu, sSqF,  off);
    }
    __shared__ float buf[8][4];
    int w = tid >> 5, l = tid & 31;
    if (l == 0) { buf[w][0] = sAngR; buf[w][1] = sSqR; buf[w][2] = sAngF; buf[w][3] = sSqF; }
    __syncthreads();
    if (tid == 0) {
        float aR = 0.f, qR = 0.f, aF = 0.f, qF = 0.f;
        #pragma unroll
        for (int i = 0; i < NTH/32; i++) {
            aR += buf[i][0]; qR += buf[i][1]; aF += buf[i][2]; qF += buf[i][3];
        }
        float rloss = aF / (float)NFK + aR / (float)NRK;
        float tloss = qR / (float)NRK + qF / (float)NFK;
        out[0] = rloss + tloss * PI_F;
    }
}

// ---------------- launch ----------------
extern "C" void kernel_launch(void* const* d_in, const int* in_sizes, int n_in,
                              void* d_out, int out_size) {
    // Identify inputs by element count (all distinct): robust to ordering.
    const float* t_fake   = nullptr;  // 4096*3  = 12288
    const float* R_fake   = nullptr;  // 4096*9  = 36864
    const float* r_buffer = nullptr;  // 8192*9  = 73728
    const float* t_buffer = nullptr;  // 8192*3  = 24576
    for (int i = 0; i < n_in; i++) {
        switch (in_sizes[i]) {
            case NFK*3: t_fake   = (const float*)d_in[i]; break;
            case NFK*9: R_fake   = (const float*)d_in[i]; break;
            case NRK*9: r_buffer = (const float*)d_in[i]; break;
            case NRK*3: t_buffer = (const float*)d_in[i]; break;
            default: break;
        }
    }

    init_kernel<<<NRK/NTH, NTH>>>(t_fake, R_fake, t_buffer);
    dim3 grid(NCH, NRB);
    pair_kernel<<<grid, NTH>>>(r_buffer, t_buffer);
    final_kernel<<<1, NTH>>>((float*)d_out);
}

// round 2
// speedup vs baseline: 1.6768x; 1.6768x over previous
#include <cuda_runtime.h>
#include <math.h>

// Problem constants (fixed shapes per reference)
#define NFK 4096
#define NRK 8192
#define NTH 256
#define NT 4                    // r rows per thread (2 packed pairs)
#define RBLK (NTH*NT)           // 1024 r per block
#define FCHUNK 128              // f columns per block
#define NCH (NFK/FCHUNK)        // 32
#define NRB (NRK/RBLK)          // 8
#define NPB 32                  // partial-reduction blocks

#define EPS_CH   1e-5f
#define EPS_ACOS 1e-6f
#define PI_F     3.14159265358979323846f

// ---------------- scratch (static device memory: allocation-free) ----------------
__device__ unsigned g_minu[NRK];     // min over f of (nf - 2 dot), ord-encoded
__device__ unsigned g_maxtrR[NRK];   // max over f of trace, ord-encoded
__device__ unsigned g_minv[NFK];     // min over r of (nr - 2 dot), ord-encoded
__device__ unsigned g_maxtrF[NFK];   // max over r of trace, ord-encoded
__device__ float    g_part[NPB*4];   // per-block partial sums

// Order-preserving float<->uint mapping (atomic/REDUX min/max on floats).
__device__ __forceinline__ unsigned ford(float f) {
    unsigned u = __float_as_uint(f);
    return (u & 0x80000000u) ? ~u : (u | 0x80000000u);
}
__device__ __forceinline__ float finv(unsigned u) {
    return __uint_as_float((u & 0x80000000u) ? (u & 0x7fffffffu) : ~u);
}

// ---------------- packed f32x2 helpers ----------------
__device__ __forceinline__ unsigned long long pk2(float a, float b) {
    unsigned long long r;
    asm("mov.b64 %0, {%1, %2};" : "=l"(r) : "f"(a), "f"(b));
    return r;
}
__device__ __forceinline__ unsigned long long ffma2(unsigned long long a,
                                                    unsigned long long b,
                                                    unsigned long long c) {
    unsigned long long d;
    asm("fma.rn.f32x2 %0, %1, %2, %3;" : "=l"(d) : "l"(a), "l"(b), "l"(c));
    return d;
}
__device__ __forceinline__ unsigned long long fmul2(unsigned long long a,
                                                    unsigned long long b) {
    unsigned long long d;
    asm("mul.rn.f32x2 %0, %1, %2;" : "=l"(d) : "l"(a), "l"(b));
    return d;
}
__device__ __forceinline__ float f2lo(unsigned long long v) {
    return __uint_as_float((unsigned)v);
}
__device__ __forceinline__ float f2hi(unsigned long long v) {
    return __uint_as_float((unsigned)(v >> 32));
}

// ---------------- reset scratch ----------------
__global__ void reset_kernel() {
    int i = blockIdx.x * blockDim.x + threadIdx.x;
    if (i < NRK) { g_minu[i] = 0xFFFFFFFFu; g_maxtrR[i] = 0u; }
    if (i < NFK) { g_minv[i] = 0xFFFFFFFFu; g_maxtrF[i] = 0u; }
}

// ---------------- main all-pairs kernel ----------------
// Shared f-tile layout: per f, 14 float2 slots (112 B, 16B-aligned), each value
// DUPLICATED (v,v) so LDS.128 yields ready-to-use packed-broadcast operands:
// slot 0:(tx,tx) 1:(ty,ty) 2:(tz,tz) 3:(nf,nf) 4..12:(R0..R8 dup) 13:pad
__global__ __launch_bounds__(NTH, 2)
void pair_kernel(const float* __restrict__ t_fake,
                 const float* __restrict__ R_fake,
                 const float* __restrict__ r_buffer,
                 const float* __restrict__ t_buffer) {
    __shared__ __align__(16) float sf[FCHUNK * 28];

    const int fbase = blockIdx.x * FCHUNK;
    const int rbase = blockIdx.y * RBLK;
    const int tid   = threadIdx.x;
    const int lane  = tid & 31;

    // Stage duplicated f-tile: 12 raw values per f
    for (int i = tid; i < FCHUNK * 12; i += NTH) {
        int fl = i / 12, v = i - fl * 12;
        int fg = fbase + fl;
        float val = (v < 3) ? t_fake[fg * 3 + v] : R_fake[fg * 9 + (v - 3)];
        int slot = (v < 3) ? v : (v + 1);
        sf[fl * 28 + slot * 2 + 0] = val;
        sf[fl * 28 + slot * 2 + 1] = val;
    }
    // nf slot
    for (int fl = tid; fl < FCHUNK; fl += NTH) {
        int fg = fbase + fl;
        float tx = t_fake[fg * 3 + 0], ty = t_fake[fg * 3 + 1], tz = t_fake[fg * 3 + 2];
        float nf = fmaf(tx, tx, fmaf(ty, ty, tz * tz));
        sf[fl * 28 + 6] = nf;
        sf[fl * 28 + 7] = nf;
    }
    __syncthreads();

    // r-side: NT=4 rows as 2 packed pairs, register-resident.
    const int r0 = rbase + tid * NT;
    unsigned long long tb2[2][3], Rr2[2][9], nr2[2];
    #pragma unroll
    for (int jp = 0; jp < 2; jp++) {
        int ra = r0 + 2 * jp, rb = ra + 1;
        float ax = t_buffer[ra*3+0], ay = t_buffer[ra*3+1], az = t_buffer[ra*3+2];
        float bx = t_buffer[rb*3+0], by = t_buffer[rb*3+1], bz = t_buffer[rb*3+2];
        tb2[jp][0] = pk2(ax, bx);
        tb2[jp][1] = pk2(ay, by);
        tb2[jp][2] = pk2(az, bz);
        nr2[jp] = pk2(fmaf(ax, ax, fmaf(ay, ay, az * az)),
                      fmaf(bx, bx, fmaf(by, by, bz * bz)));
        #pragma unroll
        for (int k = 0; k < 9; k++)
            Rr2[jp][k] = pk2(r_buffer[ra*9+k], r_buffer[rb*9+k]);
    }
    const unsigned long long M2 = pk2(-2.0f, -2.0f);

    const float INF = __int_as_float(0x7f800000);
    float minu[NT], maxtr[NT];
    #pragma unroll
    for (int j = 0; j < NT; j++) { minu[j] = INF; maxtr[j] = -INF; }

    for (int f = 0; f < FCHUNK; f++) {
        const ulonglong2* fp = reinterpret_cast<const ulonglong2*>(sf + f * 28);
        ulonglong2 A = fp[0];   // tx2, ty2
        ulonglong2 B = fp[1];   // tz2, nf2
        ulonglong2 C = fp[2];   // R0, R1
        ulonglong2 D = fp[3];   // R2, R3
        ulonglong2 E = fp[4];   // R4, R5
        ulonglong2 F = fp[5];   // R6, R7
        ulonglong2 G = fp[6];   // R8, pad

        float fv = INF, ft = -INF;
        #pragma unroll
        for (int jp = 0; jp < 2; jp++) {
            unsigned long long dot =
                ffma2(tb2[jp][0], A.x, ffma2(tb2[jp][1], A.y, fmul2(tb2[jp][2], B.x)));
            unsigned long long u2 = ffma2(dot, M2, B.y);       // nf - 2 dot
            unsigned long long v2 = ffma2(dot, M2, nr2[jp]);   // nr - 2 dot
            unsigned long long tr = fmul2(Rr2[jp][0], C.x);
            tr = ffma2(Rr2[jp][1], C.y, tr);
            tr = ffma2(Rr2[jp][2], D.x, tr);
            tr = ffma2(Rr2[jp][3], D.y, tr);
            tr = ffma2(Rr2[jp][4], E.x, tr);
            tr = ffma2(Rr2[jp][5], E.y, tr);
            tr = ffma2(Rr2[jp][6], F.x, tr);
            tr = ffma2(Rr2[jp][7], F.y, tr);
            tr = ffma2(Rr2[jp][8], G.x, tr);

            minu[2*jp+0]  = fminf(minu[2*jp+0],  f2lo(u2));
            minu[2*jp+1]  = fminf(minu[2*jp+1],  f2hi(u2));
            maxtr[2*jp+0] = fmaxf(maxtr[2*jp+0], f2lo(tr));
            maxtr[2*jp+1] = fmaxf(maxtr[2*jp+1], f2hi(tr));
            fv = fminf(fv, fminf(f2lo(v2), f2hi(v2)));
            ft = fmaxf(ft, fmaxf(f2lo(tr), f2hi(tr)));
        }

        // Per-f reduction across warp lanes: single REDUX each.
        unsigned rmn = __reduce_min_sync(0xffffffffu, ford(fv));
        unsigned rmx = __reduce_max_sync(0xffffffffu, ford(ft));
        if (lane == 0) {
            atomicMin(&g_minv[fbase + f],   rmn);
            atomicMax(&g_maxtrF[fbase + f], rmx);
        }
    }

    // Per-r merge: one atomic pair per r per f-chunk.
    #pragma unroll
    for (int j = 0; j < NT; j++) {
        atomicMin(&g_minu[r0 + j],   ford(minu[j]));
        atomicMax(&g_maxtrR[r0 + j], ford(maxtr[j]));
    }
}

// ---------------- epilogue stage 1: per-block partials ----------------
__global__ void partial_kernel(const float* __restrict__ t_fake,
                               const float* __restrict__ t_buffer) {
    const int tid = threadIdx.x;
    const int gid = blockIdx.x * NTH + tid;
    const int stride = NPB * NTH;   // 8192

    float sAngR = 0.f, sSqR = 0.f, sAngF = 0.f, sSqF = 0.f;

    for (int i = gid; i < NRK; i += stride) {
        float tx = t_buffer[i*3+0], ty = t_buffer[i*3+1], tz = t_buffer[i*3+2];
        float nr = fmaf(tx, tx, fmaf(ty, ty, tz * tz));
        float td = fmaxf(nr + finv(g_minu[i]), 0.0f);
        sSqR += sqrtf(td + EPS_CH);
        float cs = 0.5f * (finv(g_maxtrR[i]) - 1.0f);
        cs = fminf(fmaxf(cs, -1.0f + EPS_ACOS), 1.0f - EPS_ACOS);
        sAngR += acosf(cs);
    }
    for (int i = gid; i < NFK; i += stride) {
        float tx = t_fake[i*3+0], ty = t_fake[i*3+1], tz = t_fake[i*3+2];
        float nf = fmaf(tx, tx, fmaf(ty, ty, tz * tz));
        float td = fmaxf(nf + finv(g_minv[i]), 0.0f);
        sSqF += sqrtf(td + EPS_CH);
        float cs = 0.5f * (finv(g_maxtrF[i]) - 1.0f);
        cs = fminf(fmaxf(cs, -1.0f + EPS_ACOS), 1.0f - EPS_ACOS);
        sAngF += acosf(cs);
    }

    // warp reduce (fixed tree: deterministic)
    #pragma unroll
    for (int off = 16; off; off >>= 1) {
        sAngR += __shfl_xor_sync(0xffffffffu, sAngR, off);
        sSqR  += __shfl_xor_sync(0xffffffffu, sSqR,  off);
        sAngF += __shfl_xor_sync(0xffffffffu, sAngF, off);
        sSqF  += __shfl_xor_sync(0xffffffffu, sSqF,  off);
    }
    __shared__ float buf[NTH/32][4];
    int w = tid >> 5, l = tid & 31;
    if (l == 0) { buf[w][0] = sAngR; buf[w][1] = sSqR; buf[w][2] = sAngF; buf[w][3] = sSqF; }
    __syncthreads();
    if (tid == 0) {
        float a0 = 0.f, a1 = 0.f, a2 = 0.f, a3 = 0.f;
        #pragma unroll
        for (int i = 0; i < NTH/32; i++) {
            a0 += buf[i][0]; a1 += buf[i][1]; a2 += buf[i][2]; a3 += buf[i][3];
        }
        g_part[blockIdx.x*4+0] = a0;
        g_part[blockIdx.x*4+1] = a1;
        g_part[blockIdx.x*4+2] = a2;
        g_part[blockIdx.x*4+3] = a3;
    }
}

// ---------------- epilogue stage 2: combine 32 partials ----------------
__global__ void final_kernel(float* __restrict__ out) {
    const int tid = threadIdx.x;         // 128 threads: warp w = component w
    const int w = tid >> 5, lane = tid & 31;
    float v = g_part[lane * 4 + w];      // 32 blocks exactly
    #pragma unroll
    for (int off = 16; off; off >>= 1)
        v += __shfl_xor_sync(0xffffffffu, v, off);
    __shared__ float s[4];
    if (lane == 0) s[w] = v;
    __syncthreads();
    if (tid == 0) {
        // components: 0:sumAngR 1:sumSqrtR 2:sumAngF 3:sumSqrtF
        float rloss = s[2] / (float)NFK + s[0] / (float)NRK;
        float tloss = s[1] / (float)NRK + s[3] / (float)NFK;
        out[0] = rloss + tloss * PI_F;
    }
}

// ---------------- launch ----------------
extern "C" void kernel_launch(void* const* d_in, const int* in_sizes, int n_in,
                              void* d_out, int out_size) {
    const float* t_fake   = nullptr;  // 4096*3
    const float* R_fake   = nullptr;  // 4096*9
    const float* r_buffer = nullptr;  // 8192*9
    const float* t_buffer = nullptr;  // 8192*3
    for (int i = 0; i < n_in; i++) {
        switch (in_sizes[i]) {
            case NFK*3: t_fake   = (const float*)d_in[i]; break;
            case NFK*9: R_fake   = (const float*)d_in[i]; break;
            case NRK*9: r_buffer = (const float*)d_in[i]; break;
            case NRK*3: t_buffer = (const float*)d_in[i]; break;
            default: break;
        }
    }

    reset_kernel<<<NRK/NTH, NTH>>>();
    dim3 grid(NCH, NRB);
    pair_kernel<<<grid, NTH>>>(t_fake, R_fake, r_buffer, t_buffer);
    partial_kernel<<<NPB, NTH>>>(t_fake, t_buffer);
    final_kernel<<<1, 128>>>((float*)d_out);
}

// round 5
// speedup vs baseline: 1.8341x; 1.0938x over previous
#include <cuda_runtime.h>
#include <math.h>

// Problem constants (fixed shapes per reference)
#define NFK 4096
#define NRK 8192
#define NTH 256
#define NT 4                    // r rows per thread (2 packed pairs)
#define RBLK (NTH*NT)           // 1024 r per tile
#define FCHUNK 128              // f columns per tile
#define NCH (NFK/FCHUNK)        // 32 f-chunks
#define NRB (NRK/RBLK)          // 8 r-blocks
#define NTILES (NCH*NRB)        // 256 tiles == grid size
#define NSLOT (NRB*8)           // 64 per-f partial slots (r-block x warp)
#define EBLK 48                 // epilogue blocks: 48*256 = NRK+NFK exactly

#define EPS_CH   1e-5f
#define EPS_ACOS 1e-6f
#define PI_F     3.14159265358979323846f

// ---------------- static device scratch (allocation-free) ----------------
// No cross-replay mutable state except g_done, which is monotonic and used
// mod EBLK (exactly EBLK increments per run -> exactly one finisher per run).
__device__ unsigned g_done;
__device__ uint2    g_rpart[NCH * NRK];    // [cx][r]   : (min_u ord, max_tr ord)
__device__ uint2    g_fpart[NSLOT * NFK];  // [slot][f] : (min_v ord, max_tr ord)
__device__ float    g_psum[EBLK * 4];      // per-epilogue-block partial sums

// Order-preserving float<->uint mapping (min/max in integer domain).
__device__ __forceinline__ unsigned ford(float f) {
    unsigned u = __float_as_uint(f);
    return (u & 0x80000000u) ? ~u : (u | 0x80000000u);
}
__device__ __forceinline__ float finv(unsigned u) {
    return __uint_as_float((u & 0x80000000u) ? (u & 0x7fffffffu) : ~u);
}

// ---------------- packed f32x2 helpers ----------------
__device__ __forceinline__ unsigned long long pk2(float a, float b) {
    unsigned long long r;
    asm("mov.b64 %0, {%1, %2};" : "=l"(r) : "f"(a), "f"(b));
    return r;
}
__device__ __forceinline__ unsigned long long ffma2(unsigned long long a,
                                                    unsigned long long b,
                                                    unsigned long long c) {
    unsigned long long d;
    asm("fma.rn.f32x2 %0, %1, %2, %3;" : "=l"(d) : "l"(a), "l"(b), "l"(c));
    return d;
}
__device__ __forceinline__ unsigned long long fmul2(unsigned long long a,
                                                    unsigned long long b) {
    unsigned long long d;
    asm("mul.rn.f32x2 %0, %1, %2;" : "=l"(d) : "l"(a), "l"(b));
    return d;
}
__device__ __forceinline__ float f2lo(unsigned long long v) {
    return __uint_as_float((unsigned)v);
}
__device__ __forceinline__ float f2hi(unsigned long long v) {
    return __uint_as_float((unsigned)(v >> 32));
}

// ---------------- all-pairs kernel: one tile per block ----------------
// Shared f-tile layout: per f, 14 float2 slots (112 B), each value duplicated
// (v,v) so LDS.128 yields ready-to-use packed-broadcast operands:
// slot 0:(tx) 1:(ty) 2:(tz) 3:(nf) 4..12:(R0..R8) 13:pad
__global__ __launch_bounds__(NTH, 2)
void pair_kernel(const float* __restrict__ t_fake,
                 const float* __restrict__ R_fake,
                 const float* __restrict__ r_buffer,
                 const float* __restrict__ t_buffer) {
    __shared__ __align__(16) float sf[FCHUNK * 28];

    const int tid  = threadIdx.x;
    const int lane = tid & 31;
    const int warp = tid >> 5;

    const int cx = blockIdx.x & (NCH - 1);
    const int ry = blockIdx.x >> 5;
    const int fbase = cx * FCHUNK;
    const int rbase = ry * RBLK;

    // ---- stage duplicated f-tile (12 raw values per f) ----
    for (int i = tid; i < FCHUNK * 12; i += NTH) {
        int fl = i / 12, v = i - fl * 12;
        int fg = fbase + fl;
        float val = (v < 3) ? t_fake[fg * 3 + v] : R_fake[fg * 9 + (v - 3)];
        int slot = (v < 3) ? v : (v + 1);
        sf[fl * 28 + slot * 2 + 0] = val;
        sf[fl * 28 + slot * 2 + 1] = val;
    }
    for (int fl = tid; fl < FCHUNK; fl += NTH) {
        int fg = fbase + fl;
        float tx = t_fake[fg*3+0], ty = t_fake[fg*3+1], tz = t_fake[fg*3+2];
        float nf = fmaf(tx, tx, fmaf(ty, ty, tz * tz));
        sf[fl * 28 + 6] = nf;
        sf[fl * 28 + 7] = nf;
    }

    // ---- r-side registers: 4 rows as 2 packed pairs ----
    const int r0 = rbase + tid * NT;
    unsigned long long tb2[2][3], Rr2[2][9], nr2[2];
    #pragma unroll
    for (int jp = 0; jp < 2; jp++) {
        int ra = r0 + 2 * jp, rb = ra + 1;
        float ax = t_buffer[ra*3+0], ay = t_buffer[ra*3+1], az = t_buffer[ra*3+2];
        float bx = t_buffer[rb*3+0], by = t_buffer[rb*3+1], bz = t_buffer[rb*3+2];
        tb2[jp][0] = pk2(ax, bx);
        tb2[jp][1] = pk2(ay, by);
        tb2[jp][2] = pk2(az, bz);
        nr2[jp] = pk2(fmaf(ax, ax, fmaf(ay, ay, az * az)),
                      fmaf(bx, bx, fmaf(by, by, bz * bz)));
        #pragma unroll
        for (int k = 0; k < 9; k++)
            Rr2[jp][k] = pk2(r_buffer[ra*9+k], r_buffer[rb*9+k]);
    }
    __syncthreads();

    const float INF = __int_as_float(0x7f800000);
    const unsigned long long M2 = pk2(-2.0f, -2.0f);
    float minu[NT], maxtr[NT];
    #pragma unroll
    for (int j = 0; j < NT; j++) { minu[j] = INF; maxtr[j] = -INF; }

    uint2* fslot = &g_fpart[(ry * 8 + warp) * NFK + fbase];

    #pragma unroll 2
    for (int f = 0; f < FCHUNK; f++) {
        const ulonglong2* fp = reinterpret_cast<const ulonglong2*>(sf + f * 28);
        ulonglong2 A = fp[0];   // tx2, ty2
        ulonglong2 B = fp[1];   // tz2, nf2
        ulonglong2 C = fp[2];   // R0, R1
        ulonglong2 D = fp[3];   // R2, R3
        ulonglong2 E = fp[4];   // R4, R5
        ulonglong2 F = fp[5];   // R6, R7
        ulonglong2 G = fp[6];   // R8, pad

        unsigned long long v2s[2], trs[2];
        #pragma unroll
        for (int jp = 0; jp < 2; jp++) {
            unsigned long long dot =
                ffma2(tb2[jp][0], A.x, ffma2(tb2[jp][1], A.y, fmul2(tb2[jp][2], B.x)));
            unsigned long long u2 = ffma2(dot, M2, B.y);       // nf - 2 dot
            v2s[jp] = ffma2(dot, M2, nr2[jp]);                 // nr - 2 dot
            unsigned long long tr = fmul2(Rr2[jp][0], C.x);
            tr = ffma2(Rr2[jp][1], C.y, tr);
            tr = ffma2(Rr2[jp][2], D.x, tr);
            tr = ffma2(Rr2[jp][3], D.y, tr);
            tr = ffma2(Rr2[jp][4], E.x, tr);
            tr = ffma2(Rr2[jp][5], E.y, tr);
            tr = ffma2(Rr2[jp][6], F.x, tr);
            tr = ffma2(Rr2[jp][7], F.y, tr);
            tr = ffma2(Rr2[jp][8], G.x, tr);
            trs[jp] = tr;

            minu[2*jp+0]  = fminf(minu[2*jp+0],  f2lo(u2));
            minu[2*jp+1]  = fminf(minu[2*jp+1],  f2hi(u2));
            maxtr[2*jp+0] = fmaxf(maxtr[2*jp+0], f2lo(tr));
            maxtr[2*jp+1] = fmaxf(maxtr[2*jp+1], f2hi(tr));
        }
        float fv = fminf(fminf(f2lo(v2s[0]), f2hi(v2s[0])),
                         fminf(f2lo(v2s[1]), f2hi(v2s[1])));
        float ft = fmaxf(fmaxf(f2lo(trs[0]), f2hi(trs[0])),
                         fmaxf(f2lo(trs[1]), f2hi(trs[1])));

        unsigned rmn = __reduce_min_sync(0xffffffffu, ford(fv));
        unsigned rmx = __reduce_max_sync(0xffffffffu, ford(ft));
        if (lane == 0) fslot[f] = make_uint2(rmn, rmx);
    }

    // ---- per-r partials: plain stores to disjoint addresses, no atomics ----
    #pragma unroll
    for (int j = 0; j < NT; j++)
        g_rpart[cx * NRK + r0 + j] = make_uint2(ford(minu[j]), ford(maxtr[j]));
}

// ---------------- epilogue: reduce partials, sqrt/acos, fixed-order sum ----------------
// Grid is exactly (NRK+NFK)/NTH = 48 blocks; gid < NRK -> r item, else f item.
__global__ __launch_bounds__(NTH, 4)
void epilogue_kernel(const float* __restrict__ t_fake,
                     const float* __restrict__ t_buffer,
                     float* __restrict__ out) {
    const int tid = threadIdx.x;
    const int gid = blockIdx.x * NTH + tid;    // 0 .. NRK+NFK-1 (12287)

    float sAngR = 0.f, sSqR = 0.f, sAngF = 0.f, sSqF = 0.f;

    if (gid < NRK) {
        // one r per thread: reduce 32 chunk-partials
        unsigned mn = 0xFFFFFFFFu, mx = 0u;
        #pragma unroll 8
        for (int c = 0; c < NCH; c++) {
            uint2 p = g_rpart[c * NRK + gid];
            mn = umin(mn, p.x);
            mx = umax(mx, p.y);
        }
        float tx = t_buffer[gid*3+0], ty = t_buffer[gid*3+1], tz = t_buffer[gid*3+2];
        float nr = fmaf(tx, tx, fmaf(ty, ty, tz * tz));
        float td = fmaxf(nr + finv(mn), 0.0f);
        sSqR = sqrtf(td + EPS_CH);
        float cs = 0.5f * (finv(mx) - 1.0f);
        cs = fminf(fmaxf(cs, -1.0f + EPS_ACOS), 1.0f - EPS_ACOS);
        sAngR = acosf(cs);
    } else {
        // one f per thread (f = gid - NRK in [0, NFK)): reduce 64 slot-partials
        const int f = gid - NRK;
        unsigned mn = 0xFFFFFFFFu, mx = 0u;
        #pragma unroll 8
        for (int s = 0; s < NSLOT; s++) {
            uint2 p = g_fpart[s * NFK + f];
            mn = umin(mn, p.x);
            mx = umax(mx, p.y);
        }
        float tx = t_fake[f*3+0], ty = t_fake[f*3+1], tz = t_fake[f*3+2];
        float nf = fmaf(tx, tx, fmaf(ty, ty, tz * tz));
        float td = fmaxf(nf + finv(mn), 0.0f);
        sSqF = sqrtf(td + EPS_CH);
        float cs = 0.5f * (finv(mx) - 1.0f);
        cs = fminf(fmaxf(cs, -1.0f + EPS_ACOS), 1.0f - EPS_ACOS);
        sAngF = acosf(cs);
    }

    // fixed-tree block reduction (deterministic)
    #pragma unroll
    for (int off = 16; off; off >>= 1) {
        sAngR += __shfl_xor_sync(0xffffffffu, sAngR, off);
        sSqR  += __shfl_xor_sync(0xffffffffu, sSqR,  off);
        sAngF += __shfl_xor_sync(0xffffffffu, sAngF, off);
        sSqF  += __shfl_xor_sync(0xffffffffu, sSqF,  off);
    }
    __shared__ float buf[NTH/32][4];
    int w = tid >> 5, l = tid & 31;
    if (l == 0) { buf[w][0] = sAngR; buf[w][1] = sSqR; buf[w][2] = sAngF; buf[w][3] = sSqF; }
    __syncthreads();

    if (tid == 0) {
        float a0 = 0.f, a1 = 0.f, a2 = 0.f, a3 = 0.f;
        #pragma unroll
        for (int i = 0; i < NTH/32; i++) {
            a0 += buf[i][0]; a1 += buf[i][1]; a2 += buf[i][2]; a3 += buf[i][3];
        }
        g_psum[blockIdx.x*4+0] = a0;
        g_psum[blockIdx.x*4+1] = a1;
        g_psum[blockIdx.x*4+2] = a2;
        g_psum[blockIdx.x*4+3] = a3;

        __threadfence();
        unsigned old = atomicAdd(&g_done, 1u);
        if ((old % EBLK) == (EBLK - 1)) {
            // exactly one finisher per run: fixed-order final combine
            __threadfence();
            float c0 = 0.f, c1 = 0.f, c2 = 0.f, c3 = 0.f;
            for (int i = 0; i < EBLK; i++) {
                c0 += g_psum[i*4+0]; c1 += g_psum[i*4+1];
                c2 += g_psum[i*4+2]; c3 += g_psum[i*4+3];
            }
            float rloss = c2 / (float)NFK + c0 / (float)NRK;
            float tloss = c1 / (float)NRK + c3 / (float)NFK;
            out[0] = rloss + tloss * PI_F;
        }
    }
}

// ---------------- launch ----------------
extern "C" void kernel_launch(void* const* d_in, const int* in_sizes, int n_in,
                              void* d_out, int out_size) {
    const float* t_fake   = nullptr;  // 4096*3
    const float* R_fake   = nullptr;  // 4096*9
    const float* r_buffer = nullptr;  // 8192*9
    const float* t_buffer = nullptr;  // 8192*3
    for (int i = 0; i < n_in; i++) {
        switch (in_sizes[i]) {
            case NFK*3: t_fake   = (const float*)d_in[i]; break;
            case NFK*9: R_fake   = (const float*)d_in[i]; break;
            case NRK*9: r_buffer = (const float*)d_in[i]; break;
            case NRK*3: t_buffer = (const float*)d_in[i]; break;
            default: break;
        }
    }

    pair_kernel<<<NTILES, NTH>>>(t_fake, R_fake, r_buffer, t_buffer);
    epilogue_kernel<<<EBLK, NTH>>>(t_fake, t_buffer, (float*)d_out);
}